// round 6
// baseline (speedup 1.0000x reference)
#include <cuda_runtime.h>
#include <cuda_bf16.h>
#include <cstddef>

// Problem dims (fixed):
// NB=4 blocks, H=8 heads, B=2 batch, S=1024 seq, D=HID=512.
// Algebraic optimization: combined probability matrix per (block,batch):
//   P = sum_h gate[n,h] * softmax(s[n,h] * scores)   then  HS = P @ V
// and output = MOD * ( concat_n(HS_n) @ concat_n(Wo_n) + sum_n bo_n ).

#define MODV 1.55f
#define SCALEV 0.044194173824159216f   // 1/sqrt(512)

// ---- scratch (device globals; no allocation allowed) ----
__device__ float g_Q [4u*2048u*512u];   // [NB][B*S][HID]
__device__ float g_K [4u*2048u*512u];
__device__ float g_V [4u*2048u*512u];
__device__ float g_S [8u*1024u*1024u];  // [(n*B+b)][s][t], reused for combined P
__device__ float g_HS[4u*2048u*512u];   // [NB][B*S][HID]

// ============================================================
// Generic fp32 tiled GEMM: C = alpha * A@B (+bias), batched by blockIdx.z
// Tile: BM=128, BN=64, BK=16; 256 threads, 8x4 micro-tile.
// All dims assumed multiples of the tile (true for this problem).
// ============================================================
template<bool TRANSB, bool BIAS>
__global__ void __launch_bounds__(256) gemm_f32(
    const float* __restrict__ A, size_t sAz, int lda,
    const float* __restrict__ B, size_t sBz, int ldb,
    const float* __restrict__ bias, size_t sBiasz,
    float* __restrict__ C, size_t sCz, int ldc,
    int K, float alpha)
{
    __shared__ float As[16][128];
    __shared__ float Bs[16][64];

    const int z = blockIdx.z;
    A += (size_t)z * sAz;
    B += (size_t)z * sBz;
    C += (size_t)z * sCz;
    if (BIAS) bias += (size_t)z * sBiasz;

    const int m0 = blockIdx.y * 128;
    const int n0 = blockIdx.x * 64;
    const int tid  = threadIdx.x;
    const int trow = tid >> 4;   // 0..15
    const int tcol = tid & 15;   // 0..15

    float acc[8][4];
#pragma unroll
    for (int i = 0; i < 8; i++)
#pragma unroll
        for (int j = 0; j < 4; j++) acc[i][j] = 0.f;

    for (int k0 = 0; k0 < K; k0 += 16) {
        // --- load A tile (128 x 16), transposed into As[k][m] ---
#pragma unroll
        for (int j = 0; j < 2; j++) {
            int id = tid * 2 + j;          // 0..511
            int r  = id >> 2;              // 0..127
            int c4 = id & 3;               // 0..3
            const float4 v = *(const float4*)(A + (size_t)(m0 + r) * lda + k0 + c4 * 4);
            As[c4*4+0][r] = v.x; As[c4*4+1][r] = v.y;
            As[c4*4+2][r] = v.z; As[c4*4+3][r] = v.w;
        }
        // --- load B tile ---
        if (!TRANSB) {
            int r  = tid >> 4;             // 0..15 (k)
            int c4 = tid & 15;             // 0..15 (n/4)
            *(float4*)&Bs[r][c4*4] =
                *(const float4*)(B + (size_t)(k0 + r) * ldb + n0 + c4 * 4);
        } else {
            // B is [N,K] row-major; Bs[k][n] = B[n0+n][k0+k]
            int r  = tid >> 2;             // 0..63 (n)
            int c4 = tid & 3;              // 0..3
            const float4 v = *(const float4*)(B + (size_t)(n0 + r) * ldb + k0 + c4 * 4);
            Bs[c4*4+0][r] = v.x; Bs[c4*4+1][r] = v.y;
            Bs[c4*4+2][r] = v.z; Bs[c4*4+3][r] = v.w;
        }
        __syncthreads();

#pragma unroll
        for (int kk = 0; kk < 16; kk++) {
            float a[8], b[4];
#pragma unroll
            for (int i = 0; i < 8; i++) a[i] = As[kk][trow*8 + i];
#pragma unroll
            for (int j = 0; j < 4; j++) b[j] = Bs[kk][tcol*4 + j];
#pragma unroll
            for (int i = 0; i < 8; i++)
#pragma unroll
                for (int j = 0; j < 4; j++) acc[i][j] = fmaf(a[i], b[j], acc[i][j]);
        }
        __syncthreads();
    }

    // --- epilogue ---
#pragma unroll
    for (int i = 0; i < 8; i++) {
        const int m  = m0 + trow*8 + i;
        const int nn = n0 + tcol*4;
        float4 v;
        v.x = acc[i][0] * alpha;
        v.y = acc[i][1] * alpha;
        v.z = acc[i][2] * alpha;
        v.w = acc[i][3] * alpha;
        if (BIAS) {
            v.x += bias[nn+0]; v.y += bias[nn+1];
            v.z += bias[nn+2]; v.w += bias[nn+3];
        }
        *(float4*)(C + (size_t)m * ldc + nn) = v;
    }
}

// ============================================================
// Softmax-combine: one 128-thread block per (n,b,s) row of g_S (8192 rows).
// Row of 1024 scores -> combined gated softmax sum over heads, in place.
// ============================================================
__global__ void __launch_bounds__(128) softmax_combine_kernel(
    const float* __restrict__ strength, const float* __restrict__ gate)
{
    __shared__ float sm[4];
    const int r  = blockIdx.x;        // 0..8191, enumerates (n, b, s)
    const int n  = r >> 11;           // / 2048
    float* row = g_S + (size_t)r * 1024u;
    const int tid = threadIdx.x;

    float xv[8];
#pragma unroll
    for (int j = 0; j < 8; j++) xv[j] = row[tid + 128*j];

    // row max
    float m = xv[0];
#pragma unroll
    for (int j = 1; j < 8; j++) m = fmaxf(m, xv[j]);
#pragma unroll
    for (int o = 16; o; o >>= 1) m = fmaxf(m, __shfl_xor_sync(0xffffffffu, m, o));
    if ((tid & 31) == 0) sm[tid >> 5] = m;
    __syncthreads();
    m = fmaxf(fmaxf(sm[0], sm[1]), fmaxf(sm[2], sm[3]));

    float comb[8] = {0,0,0,0,0,0,0,0};
#pragma unroll 1
    for (int h = 0; h < 8; h++) {
        const float g = gate[n*8 + h];
        if (g != 0.0f) {               // uniform across block (n fixed per block)
            float s = strength[n*64 + h*9];   // diagonal element [n][h][h]
            s = fminf(fmaxf(s, 0.01f), 1.0f);
            float e[8];
            float part = 0.f;
#pragma unroll
            for (int j = 0; j < 8; j++) {
                e[j] = __expf(s * (xv[j] - m));
                part += e[j];
            }
#pragma unroll
            for (int o = 16; o; o >>= 1) part += __shfl_xor_sync(0xffffffffu, part, o);
            __syncthreads();           // protect sm from previous use
            if ((tid & 31) == 0) sm[tid >> 5] = part;
            __syncthreads();
            const float denom = sm[0] + sm[1] + sm[2] + sm[3];
            const float inv = g / denom;
#pragma unroll
            for (int j = 0; j < 8; j++) comb[j] = fmaf(e[j], inv, comb[j]);
        }
    }
#pragma unroll
    for (int j = 0; j < 8; j++) row[tid + 128*j] = comb[j];
}

// ============================================================
// Output GEMM with concatenated K over blocks:
// out[m][o] = MOD * ( sum_n HS[n][m][:] @ Wo[n][:][o] + sum_n bo[n][o] )
// M=2048, N=512, K_total = 4*512 = 2048.
// ============================================================
__global__ void __launch_bounds__(256) gemm_out_kernel(
    const float* __restrict__ Wo, const float* __restrict__ bo,
    float* __restrict__ out)
{
    __shared__ float As[16][128];
    __shared__ float Bs[16][64];

    const int m0 = blockIdx.y * 128;
    const int n0 = blockIdx.x * 64;
    const int tid  = threadIdx.x;
    const int trow = tid >> 4;
    const int tcol = tid & 15;

    float acc[8][4];
#pragma unroll
    for (int i = 0; i < 8; i++)
#pragma unroll
        for (int j = 0; j < 4; j++) acc[i][j] = 0.f;

    for (int k0 = 0; k0 < 2048; k0 += 16) {
        const int kn = k0 >> 9;        // which block n
        const int kh = k0 & 511;       // offset within HID
        const float* Abase = g_HS + (size_t)kn * 1048576u + kh;
        const float* Bbase = Wo   + (size_t)kn * 262144u + (size_t)kh * 512u;

#pragma unroll
        for (int j = 0; j < 2; j++) {
            int id = tid * 2 + j;
            int r  = id >> 2;
            int c4 = id & 3;
            const float4 v = *(const float4*)(Abase + (size_t)(m0 + r) * 512u + c4 * 4);
            As[c4*4+0][r] = v.x; As[c4*4+1][r] = v.y;
            As[c4*4+2][r] = v.z; As[c4*4+3][r] = v.w;
        }
        {
            int r  = tid >> 4;
            int c4 = tid & 15;
            *(float4*)&Bs[r][c4*4] =
                *(const float4*)(Bbase + (size_t)r * 512u + n0 + c4 * 4);
        }
        __syncthreads();

#pragma unroll
        for (int kk = 0; kk < 16; kk++) {
            float a[8], b[4];
#pragma unroll
            for (int i = 0; i < 8; i++) a[i] = As[kk][trow*8 + i];
#pragma unroll
            for (int j = 0; j < 4; j++) b[j] = Bs[kk][tcol*4 + j];
#pragma unroll
            for (int i = 0; i < 8; i++)
#pragma unroll
                for (int j = 0; j < 4; j++) acc[i][j] = fmaf(a[i], b[j], acc[i][j]);
        }
        __syncthreads();
    }

#pragma unroll
    for (int i = 0; i < 8; i++) {
        const int m = m0 + trow*8 + i;
        const int o = n0 + tcol*4;
        float4 v;
#pragma unroll
        for (int j = 0; j < 4; j++) {
            const float bsum = bo[o+j] + bo[512+o+j] + bo[1024+o+j] + bo[1536+o+j];
            ((float*)&v)[j] = MODV * (acc[i][j] + bsum);
        }
        *(float4*)(out + (size_t)m * 512u + o) = v;
    }
}

// ============================================================
extern "C" void kernel_launch(void* const* d_in, const int* in_sizes, int n_in,
                              void* d_out, int out_size)
{
    float *Q, *K, *V, *S, *HS;
    cudaGetSymbolAddress((void**)&Q,  g_Q);
    cudaGetSymbolAddress((void**)&K,  g_K);
    cudaGetSymbolAddress((void**)&V,  g_V);
    cudaGetSymbolAddress((void**)&S,  g_S);
    cudaGetSymbolAddress((void**)&HS, g_HS);

    const float* x        = (const float*)d_in[0];
    const float* Wq       = (const float*)d_in[1];
    const float* bq       = (const float*)d_in[2];
    const float* Wk       = (const float*)d_in[3];
    const float* bk       = (const float*)d_in[4];
    const float* Wv       = (const float*)d_in[5];
    const float* bv       = (const float*)d_in[6];
    const float* Wo       = (const float*)d_in[7];
    const float* bo       = (const float*)d_in[8];
    const float* strength = (const float*)d_in[9];
    const float* gate     = (const float*)d_in[10];
    float* out = (float*)d_out;

    const dim3 blk(256);

    // 1) QKV projections: [2048,512] @ [512,512] + bias, batched over n=0..3
    gemm_f32<false, true><<<dim3(8, 16, 4), blk>>>(
        x, 0, 512, Wq, 262144u, 512, bq, 512u, Q, 1048576u, 512, 512, 1.0f);
    gemm_f32<false, true><<<dim3(8, 16, 4), blk>>>(
        x, 0, 512, Wk, 262144u, 512, bk, 512u, K, 1048576u, 512, 512, 1.0f);
    gemm_f32<false, true><<<dim3(8, 16, 4), blk>>>(
        x, 0, 512, Wv, 262144u, 512, bv, 512u, V, 1048576u, 512, 512, 1.0f);

    // 2) scores = Q @ K^T / sqrt(512), per (n,b): 8 GEMMs of 1024x1024x512
    gemm_f32<true, false><<<dim3(16, 8, 8), blk>>>(
        Q, 524288u, 512, K, 524288u, 512, nullptr, 0, S, 1048576u, 1024, 512, SCALEV);

    // 3) gated multi-temperature softmax, combined over heads, in place
    softmax_combine_kernel<<<8192, 128>>>(strength, gate);

    // 4) HS = P @ V, per (n,b): 8 GEMMs of 1024x512x1024
    gemm_f32<false, false><<<dim3(8, 8, 8), blk>>>(
        S, 1048576u, 1024, V, 524288u, 512, nullptr, 0, HS, 524288u, 512, 1024, 1.0f);

    // 5) out = MOD * (concat_n HS @ concat_n Wo + sum_n bo)
    gemm_out_kernel<<<dim3(8, 16, 1), blk>>>(Wo, bo, out);
}

// round 9
// speedup vs baseline: 2.5770x; 2.5770x over previous
#include <cuda_runtime.h>
#include <cstdint>
#include <cstddef>

// NB=4, H=8, B=2, S=1024, D=HID=512.
// P = sum_h gate[n,h] * softmax(s[n,h] * scores);  HS = P @ V
// out = MOD * ( concat_n(HS_n) @ concat_n(Wo_n) + sum_n bo_n ).
#define MODV 1.55f
#define SCALEV 0.044194173824159216f   // 1/sqrt(512)

// ---- scratch (device globals; no allocation allowed) ----
__device__ float g_Q  [4u*2048u*512u];
__device__ float g_K  [4u*2048u*512u];
__device__ float g_V  [4u*2048u*512u];
__device__ float g_VT [8u*512u*1024u];   // per (n,b): V^T [h][t]
__device__ float g_S  [8u*1024u*1024u];  // scores / combined probs
__device__ float g_HS [4u*2048u*512u];
__device__ float g_WT [3u*4u*512u*512u]; // WqT, WkT, WvT: [w][n][h][d]
__device__ float g_WoT[4u*512u*512u];    // [n][o][h]

// round fp32 -> tf32 (rna), result still in 32-bit container
__device__ __forceinline__ float tf32r(float x) {
    uint32_t u;
    asm("cvt.rna.tf32.f32 %0, %1;" : "=r"(u) : "f"(x));
    return __uint_as_float(u);
}

#define MMA_TF32(c, a0, a1, a2, a3, b0, b1)                                   \
    asm volatile("mma.sync.aligned.m16n8k8.row.col.f32.tf32.tf32.f32 "        \
        "{%0,%1,%2,%3}, {%4,%5,%6,%7}, {%8,%9}, {%0,%1,%2,%3};"               \
        : "+f"((c)[0]), "+f"((c)[1]), "+f"((c)[2]), "+f"((c)[3])              \
        : "r"(a0), "r"(a1), "r"(a2), "r"(a3), "r"(b0), "r"(b1))

// SMEM tile: 128 rows x 32 k-cols, row stride 36 floats (conflict-free frags)
#define TSTRIDE 36
#define TILEF   (128 * TSTRIDE)                 // floats per tile
#define GEMM_SMEM_BYTES (4u * TILEF * 4u)       // A[2] + B[2]

// ============================================================
// tf32 tensor-core GEMM via mma.sync: C = epi(A @ B^T)
//   A: [M,K] K-major: elem[m][k] = A + z*zA + (k/512)*slabA + (k%512) + m*lda
//   B: [N,K] K-major, same slab scheme.
// Tile 128x128, BK=32, 256 threads (8 warps, each 64x32 warp-tile).
// EPI: 0 -> alpha*acc ; 1 -> acc + bias[z][n] ; 2 -> MOD*(acc + sum4 bias[n])
// ============================================================
template<int EPI>
__global__ void __launch_bounds__(256) gemm_mma(
    const float* __restrict__ A, size_t zA, size_t slabA, int lda,
    const float* __restrict__ B, size_t zB, size_t slabB, int ldb,
    const float* __restrict__ bias, size_t zBias,
    float* __restrict__ C, size_t zC, int ldc,
    int Ktot, float alpha)
{
    extern __shared__ float smx[];
    float* sA = smx;               // [2][TILEF]
    float* sB = smx + 2 * TILEF;   // [2][TILEF]

    const int tid  = threadIdx.x;
    const int wid  = tid >> 5;
    const int lane = tid & 31;
    const int g    = lane >> 2;    // 0..7
    const int tig  = lane & 3;     // 0..3
    const int wm   = wid >> 2;     // 0..1 -> 64-row slab
    const int wn   = wid & 3;      // 0..3 -> 32-col slab

    const float* Az = A + (size_t)blockIdx.z * zA;
    const float* Bz = B + (size_t)blockIdx.z * zB;
    const int m0 = blockIdx.y * 128;
    const int n0 = blockIdx.x * 128;
    const int NIT = Ktot >> 5;

    float acc[16][4];
#pragma unroll
    for (int i = 0; i < 16; i++)
#pragma unroll
        for (int j = 0; j < 4; j++) acc[i][j] = 0.f;

    // staging slots: thread covers 4 float4 per operand tile
    int rr[4], cc[4];
#pragma unroll
    for (int j = 0; j < 4; j++) { int f = tid + 256 * j; rr[j] = f >> 3; cc[j] = f & 7; }

    float4 pa[4], pb[4];
    // prefetch iter 0 (k0 = 0 -> slab 0, koff 0)
#pragma unroll
    for (int j = 0; j < 4; j++) {
        pa[j] = *(const float4*)(Az + (size_t)(m0 + rr[j]) * lda + cc[j] * 4);
        pb[j] = *(const float4*)(Bz + (size_t)(n0 + rr[j]) * ldb + cc[j] * 4);
    }
    // stage iter 0 into buffer 0 (with tf32 rounding)
#pragma unroll
    for (int j = 0; j < 4; j++) {
        float4 va = pa[j], vb = pb[j];
        va.x = tf32r(va.x); va.y = tf32r(va.y); va.z = tf32r(va.z); va.w = tf32r(va.w);
        vb.x = tf32r(vb.x); vb.y = tf32r(vb.y); vb.z = tf32r(vb.z); vb.w = tf32r(vb.w);
        *(float4*)(sA + rr[j] * TSTRIDE + cc[j] * 4) = va;
        *(float4*)(sB + rr[j] * TSTRIDE + cc[j] * 4) = vb;
    }
    __syncthreads();

    for (int it = 0; it < NIT; it++) {
        const int cur = it & 1;
        if (it + 1 < NIT) {
            const int k0 = (it + 1) << 5;
            const float* Ait = Az + (size_t)(k0 >> 9) * slabA + (k0 & 511);
            const float* Bit = Bz + (size_t)(k0 >> 9) * slabB + (k0 & 511);
#pragma unroll
            for (int j = 0; j < 4; j++) {
                pa[j] = *(const float4*)(Ait + (size_t)(m0 + rr[j]) * lda + cc[j] * 4);
                pb[j] = *(const float4*)(Bit + (size_t)(n0 + rr[j]) * ldb + cc[j] * 4);
            }
        }

        const float* a_ = sA + cur * TILEF;
        const float* b_ = sB + cur * TILEF;
#pragma unroll
        for (int k8 = 0; k8 < 4; k8++) {
            const int kk = k8 * 8;
            uint32_t bf[4][2];
#pragma unroll
            for (int nf = 0; nf < 4; nf++) {
                const float* bp = b_ + (wn * 32 + nf * 8 + g) * TSTRIDE + kk + tig;
                bf[nf][0] = __float_as_uint(bp[0]);
                bf[nf][1] = __float_as_uint(bp[4]);
            }
#pragma unroll
            for (int mf = 0; mf < 4; mf++) {
                const float* ap = a_ + (wm * 64 + mf * 16 + g) * TSTRIDE + kk + tig;
                const uint32_t a0 = __float_as_uint(ap[0]);
                const uint32_t a1 = __float_as_uint(ap[8 * TSTRIDE]);
                const uint32_t a2 = __float_as_uint(ap[4]);
                const uint32_t a3 = __float_as_uint(ap[8 * TSTRIDE + 4]);
#pragma unroll
                for (int nf = 0; nf < 4; nf++)
                    MMA_TF32(acc[mf * 4 + nf], a0, a1, a2, a3, bf[nf][0], bf[nf][1]);
            }
        }

        if (it + 1 < NIT) {
            __syncthreads();
            float* dA = sA + ((it + 1) & 1) * TILEF;
            float* dB = sB + ((it + 1) & 1) * TILEF;
#pragma unroll
            for (int j = 0; j < 4; j++) {
                float4 va = pa[j], vb = pb[j];
                va.x = tf32r(va.x); va.y = tf32r(va.y); va.z = tf32r(va.z); va.w = tf32r(va.w);
                vb.x = tf32r(vb.x); vb.y = tf32r(vb.y); vb.z = tf32r(vb.z); vb.w = tf32r(vb.w);
                *(float4*)(dA + rr[j] * TSTRIDE + cc[j] * 4) = va;
                *(float4*)(dB + rr[j] * TSTRIDE + cc[j] * 4) = vb;
            }
            __syncthreads();
        }
    }

    // ---- epilogue ----
    float* Cz = C + (size_t)blockIdx.z * zC;
    const float* biasz = (EPI == 1) ? (bias + (size_t)blockIdx.z * zBias) : bias;

#pragma unroll
    for (int mf = 0; mf < 4; mf++) {
        const int r0 = m0 + wm * 64 + mf * 16 + g;
#pragma unroll
        for (int nf = 0; nf < 4; nf++) {
            const int col = n0 + wn * 32 + nf * 8 + 2 * tig;
            float* c = acc[mf * 4 + nf];
            float o0, o1, o2, o3;
            if (EPI == 0) {
                o0 = c[0] * alpha; o1 = c[1] * alpha;
                o2 = c[2] * alpha; o3 = c[3] * alpha;
            } else if (EPI == 1) {
                const float b0v = biasz[col], b1v = biasz[col + 1];
                o0 = c[0] + b0v; o1 = c[1] + b1v;
                o2 = c[2] + b0v; o3 = c[3] + b1v;
            } else {
                const float b0v = bias[col] + bias[512 + col] + bias[1024 + col] + bias[1536 + col];
                const float b1v = bias[col + 1] + bias[512 + col + 1] +
                                  bias[1024 + col + 1] + bias[1536 + col + 1];
                o0 = MODV * (c[0] + b0v); o1 = MODV * (c[1] + b1v);
                o2 = MODV * (c[2] + b0v); o3 = MODV * (c[3] + b1v);
            }
            float2 v01 = make_float2(o0, o1);
            float2 v23 = make_float2(o2, o3);
            *(float2*)(Cz + (size_t)r0 * ldc + col) = v01;
            *(float2*)(Cz + (size_t)(r0 + 8) * ldc + col) = v23;
        }
    }
}

// ============================================================
// batched 32x32 tiled transpose: out[z][c][r] = in[z][r][c]
// ============================================================
__global__ void __launch_bounds__(256) transpose_kernel(
    const float* __restrict__ in, float* __restrict__ out, int R, int Cc)
{
    __shared__ float t[32][33];
    const size_t zoff = (size_t)blockIdx.z * R * Cc;
    in += zoff; out += zoff;
    const int c0 = blockIdx.x * 32, r0 = blockIdx.y * 32;
    const int x = threadIdx.x, y = threadIdx.y;
#pragma unroll
    for (int j = 0; j < 32; j += 8)
        t[y + j][x] = in[(size_t)(r0 + y + j) * Cc + c0 + x];
    __syncthreads();
#pragma unroll
    for (int j = 0; j < 32; j += 8)
        out[(size_t)(c0 + y + j) * R + r0 + x] = t[x][y + j];
}

// ============================================================
// Softmax-combine: 8192 rows of 1024, in place in g_S
// ============================================================
__global__ void __launch_bounds__(128) softmax_combine_kernel(
    const float* __restrict__ strength, const float* __restrict__ gate)
{
    __shared__ float sm[4];
    const int r   = blockIdx.x;
    const int n   = r >> 11;
    float* row = g_S + (size_t)r * 1024u;
    const int tid = threadIdx.x;

    float xv[8];
#pragma unroll
    for (int j = 0; j < 8; j++) xv[j] = row[tid + 128 * j];

    float m = xv[0];
#pragma unroll
    for (int j = 1; j < 8; j++) m = fmaxf(m, xv[j]);
#pragma unroll
    for (int o = 16; o; o >>= 1) m = fmaxf(m, __shfl_xor_sync(0xffffffffu, m, o));
    if ((tid & 31) == 0) sm[tid >> 5] = m;
    __syncthreads();
    m = fmaxf(fmaxf(sm[0], sm[1]), fmaxf(sm[2], sm[3]));

    float comb[8] = {0,0,0,0,0,0,0,0};
#pragma unroll 1
    for (int h = 0; h < 8; h++) {
        const float g = gate[n * 8 + h];
        if (g != 0.0f) {
            float s = strength[n * 64 + h * 9];
            s = fminf(fmaxf(s, 0.01f), 1.0f);
            float e[8];
            float part = 0.f;
#pragma unroll
            for (int j = 0; j < 8; j++) { e[j] = __expf(s * (xv[j] - m)); part += e[j]; }
#pragma unroll
            for (int o = 16; o; o >>= 1) part += __shfl_xor_sync(0xffffffffu, part, o);
            __syncthreads();
            if ((tid & 31) == 0) sm[tid >> 5] = part;
            __syncthreads();
            const float inv = g / (sm[0] + sm[1] + sm[2] + sm[3]);
#pragma unroll
            for (int j = 0; j < 8; j++) comb[j] = fmaf(e[j], inv, comb[j]);
        }
    }
#pragma unroll
    for (int j = 0; j < 8; j++) row[tid + 128 * j] = comb[j];
}

// ============================================================
extern "C" void kernel_launch(void* const* d_in, const int* in_sizes, int n_in,
                              void* d_out, int out_size)
{
    float *Q, *K, *V, *VT, *S, *HS, *WT, *WoT;
    cudaGetSymbolAddress((void**)&Q,   g_Q);
    cudaGetSymbolAddress((void**)&K,   g_K);
    cudaGetSymbolAddress((void**)&V,   g_V);
    cudaGetSymbolAddress((void**)&VT,  g_VT);
    cudaGetSymbolAddress((void**)&S,   g_S);
    cudaGetSymbolAddress((void**)&HS,  g_HS);
    cudaGetSymbolAddress((void**)&WT,  g_WT);
    cudaGetSymbolAddress((void**)&WoT, g_WoT);

    const float* x        = (const float*)d_in[0];
    const float* Wq       = (const float*)d_in[1];
    const float* bq       = (const float*)d_in[2];
    const float* Wk       = (const float*)d_in[3];
    const float* bk       = (const float*)d_in[4];
    const float* Wv       = (const float*)d_in[5];
    const float* bv       = (const float*)d_in[6];
    const float* Wo       = (const float*)d_in[7];
    const float* bo       = (const float*)d_in[8];
    const float* strength = (const float*)d_in[9];
    const float* gate     = (const float*)d_in[10];
    float* out = (float*)d_out;

    cudaFuncSetAttribute(gemm_mma<0>, cudaFuncAttributeMaxDynamicSharedMemorySize, GEMM_SMEM_BYTES);
    cudaFuncSetAttribute(gemm_mma<1>, cudaFuncAttributeMaxDynamicSharedMemorySize, GEMM_SMEM_BYTES);
    cudaFuncSetAttribute(gemm_mma<2>, cudaFuncAttributeMaxDynamicSharedMemorySize, GEMM_SMEM_BYTES);

    float* WqT = WT;
    float* WkT = WT + 4u * 512u * 512u;
    float* WvT = WT + 8u * 512u * 512u;

    const dim3 tb(32, 8);
    // weight transposes: [n][d][h] -> [n][h][d]
    transpose_kernel<<<dim3(16, 16, 4), tb>>>(Wq, WqT, 512, 512);
    transpose_kernel<<<dim3(16, 16, 4), tb>>>(Wk, WkT, 512, 512);
    transpose_kernel<<<dim3(16, 16, 4), tb>>>(Wv, WvT, 512, 512);
    transpose_kernel<<<dim3(16, 16, 4), tb>>>(Wo, WoT, 512, 512);

    // 1) QKV projections: C[2048,512] = x @ W^T(n) + bias(n), z = n
    gemm_mma<1><<<dim3(4, 16, 4), 256, GEMM_SMEM_BYTES>>>(
        x, 0, 512, 512,   WqT, 262144u, 512, 512,  bq, 512u,  Q, 1048576u, 512, 512, 1.0f);
    gemm_mma<1><<<dim3(4, 16, 4), 256, GEMM_SMEM_BYTES>>>(
        x, 0, 512, 512,   WkT, 262144u, 512, 512,  bk, 512u,  K, 1048576u, 512, 512, 1.0f);
    gemm_mma<1><<<dim3(4, 16, 4), 256, GEMM_SMEM_BYTES>>>(
        x, 0, 512, 512,   WvT, 262144u, 512, 512,  bv, 512u,  V, 1048576u, 512, 512, 1.0f);

    // 2) scores = Q @ K^T / sqrt(512), z = (n,b): M=1024, N=1024, K=512
    gemm_mma<0><<<dim3(8, 8, 8), 256, GEMM_SMEM_BYTES>>>(
        Q, 524288u, 512, 512,   K, 524288u, 512, 512,  nullptr, 0,
        S, 1048576u, 1024, 512, SCALEV);

    // 3) gated multi-temperature softmax combine (in place)
    softmax_combine_kernel<<<8192, 128>>>(strength, gate);

    // 3b) V^T per (n,b): [1024][512] -> [512][1024]
    transpose_kernel<<<dim3(16, 32, 8), tb>>>(V, VT, 1024, 512);

    // 4) HS = P @ VT^T, z = (n,b): M=1024, N=512, K=1024
    gemm_mma<0><<<dim3(4, 8, 8), 256, GEMM_SMEM_BYTES>>>(
        S, 1048576u, 512, 1024,   VT, 524288u, 512, 1024,  nullptr, 0,
        HS, 524288u, 512, 1024, 1.0f);

    // 5) out = MOD * (concat_n HS @ concat_n Wo^T + sum_n bo): M=2048, N=512, K=2048
    gemm_mma<2><<<dim3(4, 16, 1), 256, GEMM_SMEM_BYTES>>>(
        HS, 0, 1048576u, 512,   WoT, 0, 262144u, 512,  bo, 0,
        out, 0, 512, 2048, 1.0f);
}

// round 10
// speedup vs baseline: 3.3602x; 1.3039x over previous
#include <cuda_runtime.h>
#include <cstdint>
#include <cstddef>

// NB=4, H=8, B=2, S=1024, D=HID=512.
// P = sum_h gate[n,h] * softmax(s[n,h] * scores);  HS = P @ V
// out = MOD * ( concat_n(HS_n) @ concat_n(Wo_n) + sum_n bo_n ).
#define MODV 1.55f
#define SCALEV 0.044194173824159216f   // 1/sqrt(512)

// ---- scratch (device globals; no allocation allowed) ----
__device__ float g_X  [2048u*512u];      // tf32-rounded x
__device__ float g_Q  [4u*2048u*512u];
__device__ float g_K  [4u*2048u*512u];
__device__ float g_V  [4u*2048u*512u];
__device__ float g_VT [8u*512u*1024u];   // per (n,b): V^T [h][t]
__device__ float g_S  [8u*1024u*1024u];  // scores / combined probs
__device__ float g_HS [4u*2048u*512u];
__device__ float g_WT [3u*4u*512u*512u]; // WqT, WkT, WvT (tf32-rounded)
__device__ float g_WoT[4u*512u*512u];    // [n][o][h]   (tf32-rounded)
__device__ float g_OP [4u*2048u*512u];   // out split-K partials

// round fp32 -> tf32 (rna), result still in 32-bit container
__device__ __forceinline__ float tf32r(float x) {
    uint32_t u;
    asm("cvt.rna.tf32.f32 %0, %1;" : "=r"(u) : "f"(x));
    return __uint_as_float(u);
}

#define MMA_TF32(c, a0, a1, a2, a3, b0, b1)                                   \
    asm volatile("mma.sync.aligned.m16n8k8.row.col.f32.tf32.tf32.f32 "        \
        "{%0,%1,%2,%3}, {%4,%5,%6,%7}, {%8,%9}, {%0,%1,%2,%3};"               \
        : "+f"((c)[0]), "+f"((c)[1]), "+f"((c)[2]), "+f"((c)[3])              \
        : "r"(a0), "r"(a1), "r"(a2), "r"(a3), "r"(b0), "r"(b1))

#define CP_ASYNC16(dst, src)                                                   \
    asm volatile("cp.async.cg.shared.global [%0], [%1], 16;"                   \
        :: "r"(dst), "l"(src))
#define CP_COMMIT() asm volatile("cp.async.commit_group;" ::: "memory")
template<int N> __device__ __forceinline__ void cp_wait() {
    asm volatile("cp.async.wait_group %0;" :: "n"(N) : "memory");
}

// SMEM tile: 128 rows x 32 k-cols, row stride 36 floats (conflict-free frags)
#define TSTRIDE 36
#define TILEF   (128 * TSTRIDE)                  // floats per tile
#define STAGEB  (2u * TILEF * 4u)                // bytes per stage (A+B)
#define NSTAGE  3
#define GEMM_SMEM_BYTES (NSTAGE * STAGEB)        // 110592 B

// ============================================================
// tf32 tensor-core GEMM, cp.async 3-stage: C = epi(A @ B^T)
//   A: [M,K] K-major: elem[m][k] = A + z*zA + (k/512)*slabA + (k%512) + m*lda
//   B: [N,K] K-major, same slab scheme. Inputs must be tf32-valued already.
// Tile 128x128, BK=32, 256 threads (8 warps, each 64x32 warp-tile).
// EPI: 0 -> alpha*acc ; 1 -> acc + bias[z][n]
// RND: round output to tf32 (when it feeds another MMA)
// ============================================================
template<int EPI, bool RND>
__global__ void __launch_bounds__(256, 2) gemm_mma(
    const float* __restrict__ A, size_t zA, size_t slabA, int lda,
    const float* __restrict__ B, size_t zB, size_t slabB, int ldb,
    const float* __restrict__ bias, size_t zBias,
    float* __restrict__ C, size_t zC, int ldc,
    int Ktot, float alpha)
{
    extern __shared__ float smx[];
    const uint32_t sbu = (uint32_t)__cvta_generic_to_shared(smx);

    const int tid  = threadIdx.x;
    const int wid  = tid >> 5;
    const int lane = tid & 31;
    const int g    = lane >> 2;    // 0..7
    const int tig  = lane & 3;     // 0..3
    const int wm   = wid >> 2;     // 0..1 -> 64-row slab
    const int wn   = wid & 3;      // 0..3 -> 32-col slab

    const float* Az = A + (size_t)blockIdx.z * zA;
    const float* Bz = B + (size_t)blockIdx.z * zB;
    const int m0 = blockIdx.y * 128;
    const int n0 = blockIdx.x * 128;
    const int NIT = Ktot >> 5;

    // staging slots: thread covers 4 float4 per operand tile
    int rr[4], cc[4];
#pragma unroll
    for (int j = 0; j < 4; j++) { int f = tid + 256 * j; rr[j] = f >> 3; cc[j] = f & 7; }

    // issue one stage's cp.asyncs (A+B tiles for k-iter itk into stage s)
    auto issue = [&](int s, int itk) {
        const int k0   = itk << 5;
        const float* Ait = Az + (size_t)(k0 >> 9) * slabA + (k0 & 511);
        const float* Bit = Bz + (size_t)(k0 >> 9) * slabB + (k0 & 511);
        const uint32_t sbase = sbu + (uint32_t)s * STAGEB;
#pragma unroll
        for (int j = 0; j < 4; j++) {
            const uint32_t off = (uint32_t)(rr[j] * TSTRIDE + cc[j] * 4) * 4u;
            CP_ASYNC16(sbase + off,
                       Ait + (size_t)(m0 + rr[j]) * lda + cc[j] * 4);
            CP_ASYNC16(sbase + (uint32_t)TILEF * 4u + off,
                       Bit + (size_t)(n0 + rr[j]) * ldb + cc[j] * 4);
        }
    };

    float acc[16][4];
#pragma unroll
    for (int i = 0; i < 16; i++)
#pragma unroll
        for (int j = 0; j < 4; j++) acc[i][j] = 0.f;

    // prologue: fill stages 0 and 1
    issue(0, 0); CP_COMMIT();
    issue(1, 1); CP_COMMIT();

    int sc = 0, sp = 2;
    for (int it = 0; it < NIT; it++) {
        if (it < NIT - 1) cp_wait<1>(); else cp_wait<0>();
        __syncthreads();
        if (it + 2 < NIT) { issue(sp, it + 2); CP_COMMIT(); }

        const float* a_ = smx + sc * (2 * TILEF);
        const float* b_ = a_ + TILEF;
#pragma unroll
        for (int k8 = 0; k8 < 4; k8++) {
            const int kk = k8 * 8;
            uint32_t bf[4][2];
#pragma unroll
            for (int nf = 0; nf < 4; nf++) {
                const float* bp = b_ + (wn * 32 + nf * 8 + g) * TSTRIDE + kk + tig;
                bf[nf][0] = __float_as_uint(bp[0]);
                bf[nf][1] = __float_as_uint(bp[4]);
            }
#pragma unroll
            for (int mf = 0; mf < 4; mf++) {
                const float* ap = a_ + (wm * 64 + mf * 16 + g) * TSTRIDE + kk + tig;
                const uint32_t a0 = __float_as_uint(ap[0]);
                const uint32_t a1 = __float_as_uint(ap[8 * TSTRIDE]);
                const uint32_t a2 = __float_as_uint(ap[4]);
                const uint32_t a3 = __float_as_uint(ap[8 * TSTRIDE + 4]);
#pragma unroll
                for (int nf = 0; nf < 4; nf++)
                    MMA_TF32(acc[mf * 4 + nf], a0, a1, a2, a3, bf[nf][0], bf[nf][1]);
            }
        }
        sc = (sc == NSTAGE - 1) ? 0 : sc + 1;
        sp = (sp == NSTAGE - 1) ? 0 : sp + 1;
        __syncthreads();   // all reads of stage done before it is refilled
    }

    // ---- epilogue ----
    float* Cz = C + (size_t)blockIdx.z * zC;
    const float* biasz = (EPI == 1) ? (bias + (size_t)blockIdx.z * zBias) : bias;

#pragma unroll
    for (int mf = 0; mf < 4; mf++) {
        const int r0 = m0 + wm * 64 + mf * 16 + g;
#pragma unroll
        for (int nf = 0; nf < 4; nf++) {
            const int col = n0 + wn * 32 + nf * 8 + 2 * tig;
            float* c = acc[mf * 4 + nf];
            float o0, o1, o2, o3;
            if (EPI == 0) {
                o0 = c[0] * alpha; o1 = c[1] * alpha;
                o2 = c[2] * alpha; o3 = c[3] * alpha;
            } else {
                const float b0v = biasz[col], b1v = biasz[col + 1];
                o0 = c[0] + b0v; o1 = c[1] + b1v;
                o2 = c[2] + b0v; o3 = c[3] + b1v;
            }
            if (RND) { o0 = tf32r(o0); o1 = tf32r(o1); o2 = tf32r(o2); o3 = tf32r(o3); }
            *(float2*)(Cz + (size_t)r0 * ldc + col)       = make_float2(o0, o1);
            *(float2*)(Cz + (size_t)(r0 + 8) * ldc + col) = make_float2(o2, o3);
        }
    }
}

// ============================================================
// round a buffer to tf32 (float4 granularity)
// ============================================================
__global__ void __launch_bounds__(256) round_kernel(
    const float* __restrict__ in, float* __restrict__ out)
{
    const int i = blockIdx.x * 256 + threadIdx.x;
    float4 v = ((const float4*)in)[i];
    v.x = tf32r(v.x); v.y = tf32r(v.y); v.z = tf32r(v.z); v.w = tf32r(v.w);
    ((float4*)out)[i] = v;
}

// ============================================================
// batched 32x32 tiled transpose with tf32 rounding at store
// ============================================================
__global__ void __launch_bounds__(256) transpose_kernel(
    const float* __restrict__ in, float* __restrict__ out, int R, int Cc)
{
    __shared__ float t[32][33];
    const size_t zoff = (size_t)blockIdx.z * R * Cc;
    in += zoff; out += zoff;
    const int c0 = blockIdx.x * 32, r0 = blockIdx.y * 32;
    const int x = threadIdx.x, y = threadIdx.y;
#pragma unroll
    for (int j = 0; j < 32; j += 8)
        t[y + j][x] = in[(size_t)(r0 + y + j) * Cc + c0 + x];
    __syncthreads();
#pragma unroll
    for (int j = 0; j < 32; j += 8)
        out[(size_t)(c0 + y + j) * R + r0 + x] = tf32r(t[x][y + j]);
}

// ============================================================
// Softmax-combine: 8192 rows of 1024, in place in g_S; output tf32-rounded
// ============================================================
__global__ void __launch_bounds__(128) softmax_combine_kernel(
    const float* __restrict__ strength, const float* __restrict__ gate)
{
    __shared__ float sm[4];
    const int r   = blockIdx.x;
    const int n   = r >> 11;
    float* row = g_S + (size_t)r * 1024u;
    const int tid = threadIdx.x;

    float xv[8];
#pragma unroll
    for (int j = 0; j < 8; j++) xv[j] = row[tid + 128 * j];

    float m = xv[0];
#pragma unroll
    for (int j = 1; j < 8; j++) m = fmaxf(m, xv[j]);
#pragma unroll
    for (int o = 16; o; o >>= 1) m = fmaxf(m, __shfl_xor_sync(0xffffffffu, m, o));
    if ((tid & 31) == 0) sm[tid >> 5] = m;
    __syncthreads();
    m = fmaxf(fmaxf(sm[0], sm[1]), fmaxf(sm[2], sm[3]));

    float comb[8] = {0,0,0,0,0,0,0,0};
#pragma unroll 1
    for (int h = 0; h < 8; h++) {
        const float g = gate[n * 8 + h];
        if (g != 0.0f) {
            float s = strength[n * 64 + h * 9];
            s = fminf(fmaxf(s, 0.01f), 1.0f);
            float e[8];
            float part = 0.f;
#pragma unroll
            for (int j = 0; j < 8; j++) { e[j] = __expf(s * (xv[j] - m)); part += e[j]; }
#pragma unroll
            for (int o = 16; o; o >>= 1) part += __shfl_xor_sync(0xffffffffu, part, o);
            __syncthreads();
            if ((tid & 31) == 0) sm[tid >> 5] = part;
            __syncthreads();
            const float inv = g / (sm[0] + sm[1] + sm[2] + sm[3]);
#pragma unroll
            for (int j = 0; j < 8; j++) comb[j] = fmaf(e[j], inv, comb[j]);
        }
    }
#pragma unroll
    for (int j = 0; j < 8; j++) row[tid + 128 * j] = tf32r(comb[j]);
}

// ============================================================
// combine split-K partials: out = MOD*(p0+p1+p2+p3 + sum_n bo[n])
// ============================================================
__global__ void __launch_bounds__(256) combine_out_kernel(
    const float* __restrict__ bo, float* __restrict__ out)
{
    const int i = blockIdx.x * 256 + threadIdx.x;   // float4 index, 262144 total
    const int col = (i & 127) * 4;
    float4 p0 = ((const float4*)g_OP)[i];
    float4 p1 = ((const float4*)(g_OP + 1048576u))[i];
    float4 p2 = ((const float4*)(g_OP + 2097152u))[i];
    float4 p3 = ((const float4*)(g_OP + 3145728u))[i];
    float4 v;
#pragma unroll
    for (int q = 0; q < 4; q++) {
        const float bsum = bo[col + q] + bo[512 + col + q] +
                           bo[1024 + col + q] + bo[1536 + col + q];
        ((float*)&v)[q] = MODV * (((float*)&p0)[q] + ((float*)&p1)[q] +
                                  ((float*)&p2)[q] + ((float*)&p3)[q] + bsum);
    }
    ((float4*)out)[i] = v;
}

// ============================================================
extern "C" void kernel_launch(void* const* d_in, const int* in_sizes, int n_in,
                              void* d_out, int out_size)
{
    float *X, *Q, *K, *V, *VT, *S, *HS, *WT, *WoT, *OP;
    cudaGetSymbolAddress((void**)&X,   g_X);
    cudaGetSymbolAddress((void**)&Q,   g_Q);
    cudaGetSymbolAddress((void**)&K,   g_K);
    cudaGetSymbolAddress((void**)&V,   g_V);
    cudaGetSymbolAddress((void**)&VT,  g_VT);
    cudaGetSymbolAddress((void**)&S,   g_S);
    cudaGetSymbolAddress((void**)&HS,  g_HS);
    cudaGetSymbolAddress((void**)&WT,  g_WT);
    cudaGetSymbolAddress((void**)&WoT, g_WoT);
    cudaGetSymbolAddress((void**)&OP,  g_OP);

    const float* x        = (const float*)d_in[0];
    const float* Wq       = (const float*)d_in[1];
    const float* bq       = (const float*)d_in[2];
    const float* Wk       = (const float*)d_in[3];
    const float* bk       = (const float*)d_in[4];
    const float* Wv       = (const float*)d_in[5];
    const float* bv       = (const float*)d_in[6];
    const float* Wo       = (const float*)d_in[7];
    const float* bo       = (const float*)d_in[8];
    const float* strength = (const float*)d_in[9];
    const float* gate     = (const float*)d_in[10];
    float* out = (float*)d_out;

    cudaFuncSetAttribute(gemm_mma<0,false>, cudaFuncAttributeMaxDynamicSharedMemorySize, GEMM_SMEM_BYTES);
    cudaFuncSetAttribute(gemm_mma<0,true>,  cudaFuncAttributeMaxDynamicSharedMemorySize, GEMM_SMEM_BYTES);
    cudaFuncSetAttribute(gemm_mma<1,true>,  cudaFuncAttributeMaxDynamicSharedMemorySize, GEMM_SMEM_BYTES);

    float* WqT = WT;
    float* WkT = WT + 4u * 512u * 512u;
    float* WvT = WT + 8u * 512u * 512u;

    const dim3 tb(32, 8);
    // 0) round x to tf32 once
    round_kernel<<<1024, 256>>>(x, X);
    // weight transposes (tf32-rounded): [n][d][h] -> [n][h][d]
    transpose_kernel<<<dim3(16, 16, 4), tb>>>(Wq, WqT, 512, 512);
    transpose_kernel<<<dim3(16, 16, 4), tb>>>(Wk, WkT, 512, 512);
    transpose_kernel<<<dim3(16, 16, 4), tb>>>(Wv, WvT, 512, 512);
    transpose_kernel<<<dim3(16, 16, 4), tb>>>(Wo, WoT, 512, 512);

    // 1) QKV projections: C[2048,512] = X @ W^T(n) + bias(n), z = n (tf32-rounded out)
    gemm_mma<1,true><<<dim3(4, 16, 4), 256, GEMM_SMEM_BYTES>>>(
        X, 0, 512, 512,   WqT, 262144u, 512, 512,  bq, 512u,  Q, 1048576u, 512, 512, 1.0f);
    gemm_mma<1,true><<<dim3(4, 16, 4), 256, GEMM_SMEM_BYTES>>>(
        X, 0, 512, 512,   WkT, 262144u, 512, 512,  bk, 512u,  K, 1048576u, 512, 512, 1.0f);
    gemm_mma<1,true><<<dim3(4, 16, 4), 256, GEMM_SMEM_BYTES>>>(
        X, 0, 512, 512,   WvT, 262144u, 512, 512,  bv, 512u,  V, 1048576u, 512, 512, 1.0f);

    // 2) scores = Q @ K^T / sqrt(512), z = (n,b): M=1024, N=1024, K=512
    gemm_mma<0,false><<<dim3(8, 8, 8), 256, GEMM_SMEM_BYTES>>>(
        Q, 524288u, 512, 512,   K, 524288u, 512, 512,  nullptr, 0,
        S, 1048576u, 1024, 512, SCALEV);

    // 3) gated multi-temperature softmax combine (in place, tf32-rounded out)
    softmax_combine_kernel<<<8192, 128>>>(strength, gate);

    // 3b) V^T per (n,b): [1024][512] -> [512][1024]
    transpose_kernel<<<dim3(16, 32, 8), tb>>>(V, VT, 1024, 512);

    // 4) HS = P @ VT^T, z = (n,b): M=1024, N=512, K=1024 (tf32-rounded out)
    gemm_mma<0,true><<<dim3(4, 8, 8), 256, GEMM_SMEM_BYTES>>>(
        S, 1048576u, 512, 1024,   VT, 524288u, 512, 1024,  nullptr, 0,
        HS, 524288u, 512, 1024, 1.0f);

    // 5) split-K=4 out partials: z = split s, A = HS slab s, B = WoT[s]
    gemm_mma<0,false><<<dim3(4, 16, 4), 256, GEMM_SMEM_BYTES>>>(
        HS, 1048576u, 0, 512,   WoT, 262144u, 0, 512,  nullptr, 0,
        OP, 1048576u, 512, 512, 1.0f);

    // 6) out = MOD*(sum partials + sum_n bo)
    combine_out_kernel<<<1024, 256>>>(bo, out);
}

// round 11
// speedup vs baseline: 3.4544x; 1.0280x over previous
#include <cuda_runtime.h>
#include <cstdint>
#include <cstddef>

// NB=4, H=8, B=2, S=1024, D=HID=512.
// P = sum_h gate[n,h] * softmax(s[n,h] * scores);  HS = P @ V
// out = MOD * ( concat_n(HS_n) @ concat_n(Wo_n) + sum_n bo_n ).
#define MODV 1.55f
#define SCALEV 0.044194173824159216f   // 1/sqrt(512)

// ---- scratch (device globals; no allocation allowed) ----
__device__ float g_X  [2048u*512u];      // tf32-rounded x
__device__ float g_Q  [4u*2048u*512u];
__device__ float g_K  [4u*2048u*512u];
__device__ float g_V  [4u*2048u*512u];
__device__ float g_VT [8u*512u*1024u];   // per (n,b): V^T [h][t]
__device__ float g_S  [8u*1024u*1024u];  // scores / combined probs
__device__ float g_HS [4u*2048u*512u];
__device__ float g_WT [3u*4u*512u*512u]; // WqT, WkT, WvT (tf32-rounded)
__device__ float g_WoT[4u*512u*512u];    // [n][o][h]   (tf32-rounded)
__device__ float g_OP [4u*2048u*512u];   // out split-K partials

// round fp32 -> tf32 (rna), result still in 32-bit container
__device__ __forceinline__ float tf32r(float x) {
    uint32_t u;
    asm("cvt.rna.tf32.f32 %0, %1;" : "=r"(u) : "f"(x));
    return __uint_as_float(u);
}

#define MMA_TF32(c, a0, a1, a2, a3, b0, b1)                                   \
    asm volatile("mma.sync.aligned.m16n8k8.row.col.f32.tf32.tf32.f32 "        \
        "{%0,%1,%2,%3}, {%4,%5,%6,%7}, {%8,%9}, {%0,%1,%2,%3};"               \
        : "+f"((c)[0]), "+f"((c)[1]), "+f"((c)[2]), "+f"((c)[3])              \
        : "r"(a0), "r"(a1), "r"(a2), "r"(a3), "r"(b0), "r"(b1))

#define CP_ASYNC16(dst, src)                                                   \
    asm volatile("cp.async.cg.shared.global [%0], [%1], 16;"                   \
        :: "r"(dst), "l"(src))
#define CP_COMMIT() asm volatile("cp.async.commit_group;" ::: "memory")
template<int N> __device__ __forceinline__ void cp_wait() {
    asm volatile("cp.async.wait_group %0;" :: "n"(N) : "memory");
}

// SMEM tiles: A 128 x 32, B 256 x 32, row stride 36 floats (conflict-free)
#define TSTRIDE 36
#define TAF (128 * TSTRIDE)                       // A tile floats
#define TBF (256 * TSTRIDE)                       // B tile floats
#define STAGEF (TAF + TBF)
#define STAGEB (STAGEF * 4u)
#define NSTAGE 3
#define GEMM_SMEM_BYTES (NSTAGE * STAGEB)         // 165888 B

// ============================================================
// tf32 tensor-core GEMM, cp.async 3-stage: C = epi(A @ B^T)
//   A: [M,K] K-major: elem[m][k] = A + z*zA + (k/512)*slabA + (k%512) + m*lda
//   B: [N,K] K-major, same slab scheme. Inputs must be tf32-valued already.
// CTA tile 128x256, BK=32, 256 threads; 8 warps (2 M x 4 N), each 64x64.
// EPI: 0 -> alpha*acc ; 1 -> acc + bias[z][n]
// RND: round output to tf32 (when it feeds another MMA)
// ============================================================
template<int EPI, bool RND>
__global__ void __launch_bounds__(256, 1) gemm_mma(
    const float* __restrict__ A, size_t zA, size_t slabA, int lda,
    const float* __restrict__ B, size_t zB, size_t slabB, int ldb,
    const float* __restrict__ bias, size_t zBias,
    float* __restrict__ C, size_t zC, int ldc,
    int Ktot, float alpha)
{
    extern __shared__ float smx[];
    const uint32_t sbu = (uint32_t)__cvta_generic_to_shared(smx);

    const int tid  = threadIdx.x;
    const int wid  = tid >> 5;
    const int lane = tid & 31;
    const int g    = lane >> 2;    // 0..7
    const int tig  = lane & 3;     // 0..3
    const int wm   = wid & 1;      // 2 M-slabs of 64
    const int wn   = wid >> 1;     // 4 N-slabs of 64

    const float* Az = A + (size_t)blockIdx.z * zA;
    const float* Bz = B + (size_t)blockIdx.z * zB;
    const int m0 = blockIdx.y * 128;
    const int n0 = blockIdx.x * 256;
    const int NIT = Ktot >> 5;

    // issue one stage's cp.asyncs (A 128x32 + B 256x32 for k-iter itk)
    auto issue = [&](int s, int itk) {
        const int k0 = itk << 5;
        const float* Ait = Az + (size_t)(k0 >> 9) * slabA + (k0 & 511);
        const float* Bit = Bz + (size_t)(k0 >> 9) * slabB + (k0 & 511);
        const uint32_t abase = sbu + (uint32_t)s * STAGEB;
        const uint32_t bbase = abase + (uint32_t)TAF * 4u;
#pragma unroll
        for (int j = 0; j < 4; j++) {              // A: 1024 float4 slots
            const int f = tid + 256 * j;
            const int r = f >> 3, c = f & 7;
            CP_ASYNC16(abase + (uint32_t)(r * TSTRIDE + c * 4) * 4u,
                       Ait + (size_t)(m0 + r) * lda + c * 4);
        }
#pragma unroll
        for (int j = 0; j < 8; j++) {              // B: 2048 float4 slots
            const int f = tid + 256 * j;
            const int r = f >> 3, c = f & 7;
            CP_ASYNC16(bbase + (uint32_t)(r * TSTRIDE + c * 4) * 4u,
                       Bit + (size_t)(n0 + r) * ldb + c * 4);
        }
    };

    float acc[32][4];
#pragma unroll
    for (int i = 0; i < 32; i++)
#pragma unroll
        for (int j = 0; j < 4; j++) acc[i][j] = 0.f;

    // prologue: fill stages 0 and 1
    issue(0, 0); CP_COMMIT();
    issue(1, 1); CP_COMMIT();

    int sc = 0, sp = 2;
    for (int it = 0; it < NIT; it++) {
        if (it < NIT - 1) cp_wait<1>(); else cp_wait<0>();
        __syncthreads();
        if (it + 2 < NIT) { issue(sp, it + 2); CP_COMMIT(); }

        const float* a_ = smx + sc * STAGEF;
        const float* b_ = a_ + TAF;
#pragma unroll
        for (int k8 = 0; k8 < 4; k8++) {
            const int kk = k8 * 8;
            uint32_t bf[8][2];
#pragma unroll
            for (int nf = 0; nf < 8; nf++) {
                const float* bp = b_ + (wn * 64 + nf * 8 + g) * TSTRIDE + kk + tig;
                bf[nf][0] = __float_as_uint(bp[0]);
                bf[nf][1] = __float_as_uint(bp[4]);
            }
#pragma unroll
            for (int mf = 0; mf < 4; mf++) {
                const float* ap = a_ + (wm * 64 + mf * 16 + g) * TSTRIDE + kk + tig;
                const uint32_t a0 = __float_as_uint(ap[0]);
                const uint32_t a1 = __float_as_uint(ap[8 * TSTRIDE]);
                const uint32_t a2 = __float_as_uint(ap[4]);
                const uint32_t a3 = __float_as_uint(ap[8 * TSTRIDE + 4]);
#pragma unroll
                for (int nf = 0; nf < 8; nf++)
                    MMA_TF32(acc[mf * 8 + nf], a0, a1, a2, a3, bf[nf][0], bf[nf][1]);
            }
        }
        sc = (sc == NSTAGE - 1) ? 0 : sc + 1;
        sp = (sp == NSTAGE - 1) ? 0 : sp + 1;
        __syncthreads();   // all reads of stage done before it is refilled
    }

    // ---- epilogue ----
    float* Cz = C + (size_t)blockIdx.z * zC;
    const float* biasz = (EPI == 1) ? (bias + (size_t)blockIdx.z * zBias) : bias;

#pragma unroll
    for (int mf = 0; mf < 4; mf++) {
        const int r0 = m0 + wm * 64 + mf * 16 + g;
#pragma unroll
        for (int nf = 0; nf < 8; nf++) {
            const int col = n0 + wn * 64 + nf * 8 + 2 * tig;
            float* c = acc[mf * 8 + nf];
            float o0, o1, o2, o3;
            if (EPI == 0) {
                o0 = c[0] * alpha; o1 = c[1] * alpha;
                o2 = c[2] * alpha; o3 = c[3] * alpha;
            } else {
                const float b0v = biasz[col], b1v = biasz[col + 1];
                o0 = c[0] + b0v; o1 = c[1] + b1v;
                o2 = c[2] + b0v; o3 = c[3] + b1v;
            }
            if (RND) { o0 = tf32r(o0); o1 = tf32r(o1); o2 = tf32r(o2); o3 = tf32r(o3); }
            *(float2*)(Cz + (size_t)r0 * ldc + col)       = make_float2(o0, o1);
            *(float2*)(Cz + (size_t)(r0 + 8) * ldc + col) = make_float2(o2, o3);
        }
    }
}

// ============================================================
// round a buffer to tf32 (float4 granularity)
// ============================================================
__global__ void __launch_bounds__(256) round_kernel(
    const float* __restrict__ in, float* __restrict__ out)
{
    const int i = blockIdx.x * 256 + threadIdx.x;
    float4 v = ((const float4*)in)[i];
    v.x = tf32r(v.x); v.y = tf32r(v.y); v.z = tf32r(v.z); v.w = tf32r(v.w);
    ((float4*)out)[i] = v;
}

// ============================================================
// fused 4-weight transpose (Wq,Wk,Wv,Wo -> WT slabs / WoT), tf32-rounded
// z = w*4 + n, w in 0..3, n in 0..3; each [512,512] transposed
// ============================================================
__global__ void __launch_bounds__(256) transpose_w_kernel(
    const float* __restrict__ Wq, const float* __restrict__ Wk,
    const float* __restrict__ Wv, const float* __restrict__ Wo)
{
    __shared__ float t[32][33];
    const int z = blockIdx.z;
    const int w = z >> 2, n = z & 3;
    const float* src = (w == 0) ? Wq : (w == 1) ? Wk : (w == 2) ? Wv : Wo;
    float* dst = (w < 3) ? (g_WT + (size_t)w * 1048576u) : g_WoT;
    src += (size_t)n * 262144u;
    dst += (size_t)n * 262144u;
    const int c0 = blockIdx.x * 32, r0 = blockIdx.y * 32;
    const int x = threadIdx.x, y = threadIdx.y;
#pragma unroll
    for (int j = 0; j < 32; j += 8)
        t[y + j][x] = src[(size_t)(r0 + y + j) * 512u + c0 + x];
    __syncthreads();
#pragma unroll
    for (int j = 0; j < 32; j += 8)
        dst[(size_t)(c0 + y + j) * 512u + r0 + x] = tf32r(t[x][y + j]);
}

// ============================================================
// batched 32x32 tiled transpose with tf32 rounding at store (for V -> VT)
// ============================================================
__global__ void __launch_bounds__(256) transpose_kernel(
    const float* __restrict__ in, float* __restrict__ out, int R, int Cc)
{
    __shared__ float t[32][33];
    const size_t zoff = (size_t)blockIdx.z * R * Cc;
    in += zoff; out += zoff;
    const int c0 = blockIdx.x * 32, r0 = blockIdx.y * 32;
    const int x = threadIdx.x, y = threadIdx.y;
#pragma unroll
    for (int j = 0; j < 32; j += 8)
        t[y + j][x] = in[(size_t)(r0 + y + j) * Cc + c0 + x];
    __syncthreads();
#pragma unroll
    for (int j = 0; j < 32; j += 8)
        out[(size_t)(c0 + y + j) * R + r0 + x] = tf32r(t[x][y + j]);
}

// ============================================================
// Softmax-combine: 8192 rows of 1024, in place in g_S; output tf32-rounded
// ============================================================
__global__ void __launch_bounds__(128) softmax_combine_kernel(
    const float* __restrict__ strength, const float* __restrict__ gate)
{
    __shared__ float sm[4];
    const int r   = blockIdx.x;
    const int n   = r >> 11;
    float* row = g_S + (size_t)r * 1024u;
    const int tid = threadIdx.x;

    float xv[8];
#pragma unroll
    for (int j = 0; j < 8; j++) xv[j] = row[tid + 128 * j];

    float m = xv[0];
#pragma unroll
    for (int j = 1; j < 8; j++) m = fmaxf(m, xv[j]);
#pragma unroll
    for (int o = 16; o; o >>= 1) m = fmaxf(m, __shfl_xor_sync(0xffffffffu, m, o));
    if ((tid & 31) == 0) sm[tid >> 5] = m;
    __syncthreads();
    m = fmaxf(fmaxf(sm[0], sm[1]), fmaxf(sm[2], sm[3]));

    float comb[8] = {0,0,0,0,0,0,0,0};
#pragma unroll 1
    for (int h = 0; h < 8; h++) {
        const float g = gate[n * 8 + h];
        if (g != 0.0f) {
            float s = strength[n * 64 + h * 9];
            s = fminf(fmaxf(s, 0.01f), 1.0f);
            float e[8];
            float part = 0.f;
#pragma unroll
            for (int j = 0; j < 8; j++) { e[j] = __expf(s * (xv[j] - m)); part += e[j]; }
#pragma unroll
            for (int o = 16; o; o >>= 1) part += __shfl_xor_sync(0xffffffffu, part, o);
            __syncthreads();
            if ((tid & 31) == 0) sm[tid >> 5] = part;
            __syncthreads();
            const float inv = g / (sm[0] + sm[1] + sm[2] + sm[3]);
#pragma unroll
            for (int j = 0; j < 8; j++) comb[j] = fmaf(e[j], inv, comb[j]);
        }
    }
#pragma unroll
    for (int j = 0; j < 8; j++) row[tid + 128 * j] = tf32r(comb[j]);
}

// ============================================================
// combine split-K partials: out = MOD*(p0+p1+p2+p3 + sum_n bo[n])
// ============================================================
__global__ void __launch_bounds__(256) combine_out_kernel(
    const float* __restrict__ bo, float* __restrict__ out)
{
    const int i = blockIdx.x * 256 + threadIdx.x;   // float4 index, 262144 total
    const int col = (i & 127) * 4;
    float4 p0 = ((const float4*)g_OP)[i];
    float4 p1 = ((const float4*)(g_OP + 1048576u))[i];
    float4 p2 = ((const float4*)(g_OP + 2097152u))[i];
    float4 p3 = ((const float4*)(g_OP + 3145728u))[i];
    float4 v;
#pragma unroll
    for (int q = 0; q < 4; q++) {
        const float bsum = bo[col + q] + bo[512 + col + q] +
                           bo[1024 + col + q] + bo[1536 + col + q];
        ((float*)&v)[q] = MODV * (((float*)&p0)[q] + ((float*)&p1)[q] +
                                  ((float*)&p2)[q] + ((float*)&p3)[q] + bsum);
    }
    ((float4*)out)[i] = v;
}

// ============================================================
extern "C" void kernel_launch(void* const* d_in, const int* in_sizes, int n_in,
                              void* d_out, int out_size)
{
    float *X, *Q, *K, *V, *VT, *S, *HS, *WT, *WoT, *OP;
    cudaGetSymbolAddress((void**)&X,   g_X);
    cudaGetSymbolAddress((void**)&Q,   g_Q);
    cudaGetSymbolAddress((void**)&K,   g_K);
    cudaGetSymbolAddress((void**)&V,   g_V);
    cudaGetSymbolAddress((void**)&VT,  g_VT);
    cudaGetSymbolAddress((void**)&S,   g_S);
    cudaGetSymbolAddress((void**)&HS,  g_HS);
    cudaGetSymbolAddress((void**)&WT,  g_WT);
    cudaGetSymbolAddress((void**)&WoT, g_WoT);
    cudaGetSymbolAddress((void**)&OP,  g_OP);

    const float* x        = (const float*)d_in[0];
    const float* Wq       = (const float*)d_in[1];
    const float* bq       = (const float*)d_in[2];
    const float* Wk       = (const float*)d_in[3];
    const float* bk       = (const float*)d_in[4];
    const float* Wv       = (const float*)d_in[5];
    const float* bv       = (const float*)d_in[6];
    const float* Wo       = (const float*)d_in[7];
    const float* bo       = (const float*)d_in[8];
    const float* strength = (const float*)d_in[9];
    const float* gate     = (const float*)d_in[10];
    float* out = (float*)d_out;

    cudaFuncSetAttribute(gemm_mma<0,false>, cudaFuncAttributeMaxDynamicSharedMemorySize, GEMM_SMEM_BYTES);
    cudaFuncSetAttribute(gemm_mma<0,true>,  cudaFuncAttributeMaxDynamicSharedMemorySize, GEMM_SMEM_BYTES);
    cudaFuncSetAttribute(gemm_mma<1,true>,  cudaFuncAttributeMaxDynamicSharedMemorySize, GEMM_SMEM_BYTES);

    float* WqT = WT;
    float* WkT = WT + 4u * 512u * 512u;
    float* WvT = WT + 8u * 512u * 512u;

    const dim3 tb(32, 8);
    // 0) round x to tf32 once; fused weight transposes (tf32-rounded)
    round_kernel<<<1024, 256>>>(x, X);
    transpose_w_kernel<<<dim3(16, 16, 16), tb>>>(Wq, Wk, Wv, Wo);

    // 1) QKV projections: C[2048,512] = X @ W^T(n) + bias(n), z = n (tf32 out)
    gemm_mma<1,true><<<dim3(2, 16, 4), 256, GEMM_SMEM_BYTES>>>(
        X, 0, 512, 512,   WqT, 262144u, 512, 512,  bq, 512u,  Q, 1048576u, 512, 512, 1.0f);
    gemm_mma<1,true><<<dim3(2, 16, 4), 256, GEMM_SMEM_BYTES>>>(
        X, 0, 512, 512,   WkT, 262144u, 512, 512,  bk, 512u,  K, 1048576u, 512, 512, 1.0f);
    gemm_mma<1,true><<<dim3(2, 16, 4), 256, GEMM_SMEM_BYTES>>>(
        X, 0, 512, 512,   WvT, 262144u, 512, 512,  bv, 512u,  V, 1048576u, 512, 512, 1.0f);

    // 2) scores = Q @ K^T / sqrt(512), z = (n,b): M=1024, N=1024, K=512
    gemm_mma<0,false><<<dim3(4, 8, 8), 256, GEMM_SMEM_BYTES>>>(
        Q, 524288u, 512, 512,   K, 524288u, 512, 512,  nullptr, 0,
        S, 1048576u, 1024, 512, SCALEV);

    // 3) gated multi-temperature softmax combine (in place, tf32 out)
    softmax_combine_kernel<<<8192, 128>>>(strength, gate);

    // 3b) V^T per (n,b): [1024][512] -> [512][1024]
    transpose_kernel<<<dim3(16, 32, 8), tb>>>(V, VT, 1024, 512);

    // 4) HS = P @ VT^T, z = (n,b): M=1024, N=512, K=1024 (tf32 out)
    gemm_mma<0,true><<<dim3(2, 8, 8), 256, GEMM_SMEM_BYTES>>>(
        S, 1048576u, 512, 1024,   VT, 524288u, 512, 1024,  nullptr, 0,
        HS, 524288u, 512, 1024, 1.0f);

    // 5) split-K=4 out partials: z = split s, A = HS slab s, B = WoT[s]
    gemm_mma<0,false><<<dim3(2, 16, 4), 256, GEMM_SMEM_BYTES>>>(
        HS, 1048576u, 0, 512,   WoT, 262144u, 0, 512,  nullptr, 0,
        OP, 1048576u, 512, 512, 1.0f);

    // 6) out = MOD*(sum partials + sum_n bo)
    combine_out_kernel<<<1024, 256>>>(bo, out);
}